// round 12
// baseline (speedup 1.0000x reference)
#include <cuda_runtime.h>
#include <cuda_fp16.h>
#include <cstdint>

#define NN 100000
#define EE 1280000
#define FF 64
#define CAP 64   // per-node in-edge capacity; P(overflow) ~ 1e-20 for multinomial(12.8)

#define GEMM_BLOCKS ((NN + 63) / 64)       // 1563
#define FILL_BLOCKS ((EE / 4 + 255) / 256) // 1250
#define FAT_GRID (2 * GEMM_BLOCKS)         // even -> gemm, odd -> fill (tail idles)

__device__ float  g_deg[NN];
__device__ float  g_dinv[NN];
__device__ int    g_fill[NN];
__device__ int2   g_edge[(size_t)NN * CAP];   // {src, bitcast(w)}
__device__ __half g_h1h[(size_t)NN * FF];     // fp16 x@W1; after k_dinv_scale: dinv[node]*h1
__device__ float  g_h2[NN];                   // relu-dot * dinv[node]

// ---------------- init ----------------
__global__ void k_init() {
    int i = blockIdx.x * blockDim.x + threadIdx.x;
    if (i < NN) { g_fill[i] = 0; g_deg[i] = 0.0f; }
}

// ---------------- fused GEMM + bucket-fill fat kernel ----------------
__global__ void __launch_bounds__(256) k_gemm_fill(const float* __restrict__ x,
                                                   const float* __restrict__ W1,
                                                   const int* __restrict__ row,
                                                   const int* __restrict__ col,
                                                   const float* __restrict__ w) {
    __shared__ float sW[FF * FF];
    __shared__ float sx[64][68];
    int t = threadIdx.x;

    if (blockIdx.x & 1) {
        // ---------- fill role ----------
        int fb = blockIdx.x >> 1;
        if (fb >= FILL_BLOCKS) return;
        int e4 = fb * 256 + t;               // 0 .. EE/4-1
        if (e4 >= EE / 4) return;
        int4 r4 = reinterpret_cast<const int4*>(row)[e4];
        int4 c4 = reinterpret_cast<const int4*>(col)[e4];
        float4 w4 = reinterpret_cast<const float4*>(w)[e4];
        int r[4] = {r4.x, r4.y, r4.z, r4.w};
        int c[4] = {c4.x, c4.y, c4.z, c4.w};
        float ww[4] = {w4.x, w4.y, w4.z, w4.w};
        int pos[4];
#pragma unroll
        for (int i = 0; i < 4; i++) pos[i] = atomicAdd(&g_fill[c[i]], 1);
#pragma unroll
        for (int i = 0; i < 4; i++) {
            asm volatile("red.global.add.f32 [%0], %1;"
                         :: "l"(&g_deg[c[i]]), "f"(ww[i]) : "memory");
            if (pos[i] < CAP)
                g_edge[(size_t)c[i] * CAP + pos[i]] = make_int2(r[i], __float_as_int(ww[i]));
        }
        return;
    }

    // ---------- gemm role ----------
    int gb = blockIdx.x >> 1;
    int nb = gb * 64;

    {
        const float4* Wv = reinterpret_cast<const float4*>(W1);
        float4* sWv = reinterpret_cast<float4*>(sW);
#pragma unroll
        for (int i = 0; i < 4; i++) sWv[t + i * 256] = Wv[t + i * 256];
    }
#pragma unroll
    for (int i = 0; i < 4; i++) {
        int idx = t + i * 256;
        int nl = idx >> 4, kv = idx & 15;
        int node = nb + nl;
        float4 v = make_float4(0.f, 0.f, 0.f, 0.f);
        if (node < NN) v = reinterpret_cast<const float4*>(x)[(size_t)node * 16 + kv];
        *reinterpret_cast<float4*>(&sx[nl][kv * 4]) = v;
    }
    __syncthreads();

    int tx = t & 15;
    int ty = t >> 4;

    float4 acc[4];
#pragma unroll
    for (int i = 0; i < 4; i++) acc[i] = make_float4(0.f, 0.f, 0.f, 0.f);

#pragma unroll
    for (int kb = 0; kb < 16; kb++) {
        float4 xr[4];
#pragma unroll
        for (int i = 0; i < 4; i++)
            xr[i] = *reinterpret_cast<const float4*>(&sx[4 * ty + i][4 * kb]);
#pragma unroll
        for (int kk = 0; kk < 4; kk++) {
            float4 wv = *reinterpret_cast<const float4*>(&sW[(4 * kb + kk) * FF + 4 * tx]);
            float xv0 = (kk == 0) ? xr[0].x : (kk == 1) ? xr[0].y : (kk == 2) ? xr[0].z : xr[0].w;
            float xv1 = (kk == 0) ? xr[1].x : (kk == 1) ? xr[1].y : (kk == 2) ? xr[1].z : xr[1].w;
            float xv2 = (kk == 0) ? xr[2].x : (kk == 1) ? xr[2].y : (kk == 2) ? xr[2].z : xr[2].w;
            float xv3 = (kk == 0) ? xr[3].x : (kk == 1) ? xr[3].y : (kk == 2) ? xr[3].z : xr[3].w;
            acc[0].x = fmaf(xv0, wv.x, acc[0].x); acc[0].y = fmaf(xv0, wv.y, acc[0].y);
            acc[0].z = fmaf(xv0, wv.z, acc[0].z); acc[0].w = fmaf(xv0, wv.w, acc[0].w);
            acc[1].x = fmaf(xv1, wv.x, acc[1].x); acc[1].y = fmaf(xv1, wv.y, acc[1].y);
            acc[1].z = fmaf(xv1, wv.z, acc[1].z); acc[1].w = fmaf(xv1, wv.w, acc[1].w);
            acc[2].x = fmaf(xv2, wv.x, acc[2].x); acc[2].y = fmaf(xv2, wv.y, acc[2].y);
            acc[2].z = fmaf(xv2, wv.z, acc[2].z); acc[2].w = fmaf(xv2, wv.w, acc[2].w);
            acc[3].x = fmaf(xv3, wv.x, acc[3].x); acc[3].y = fmaf(xv3, wv.y, acc[3].y);
            acc[3].z = fmaf(xv3, wv.z, acc[3].z); acc[3].w = fmaf(xv3, wv.w, acc[3].w);
        }
    }

#pragma unroll
    for (int i = 0; i < 4; i++) {
        int node = nb + 4 * ty + i;
        if (node >= NN) continue;
        __half2 h01 = __floats2half2_rn(acc[i].x, acc[i].y);
        __half2 h23 = __floats2half2_rn(acc[i].z, acc[i].w);
        uint2 p = make_uint2(*reinterpret_cast<uint32_t*>(&h01),
                             *reinterpret_cast<uint32_t*>(&h23));
        *reinterpret_cast<uint2*>(&g_h1h[(size_t)node * FF + 4 * tx]) = p;
    }
}

// ---------------- fused dinv + in-place scale of h1h ----------------
// 8 threads per node; each thread scales 8 halves (one uint4 = 16 bytes).
__global__ void __launch_bounds__(256) k_dinv_scale() {
    int t = blockIdx.x * blockDim.x + threadIdx.x;   // 0 .. NN*8-1
    if (t >= NN * 8) return;
    int node = t >> 3;
    float dc = rsqrtf(g_deg[node] + 1.0f);   // + self-loop weight
    if ((t & 7) == 0) g_dinv[node] = dc;
    __half2 d2 = __floats2half2_rn(dc, dc);
    uint4* p = reinterpret_cast<uint4*>(&g_h1h[(size_t)t * 8]);   // 8 halves = 16B
    uint4 v = *p;
    __half2 a = __hmul2(*reinterpret_cast<__half2*>(&v.x), d2);
    __half2 b = __hmul2(*reinterpret_cast<__half2*>(&v.y), d2);
    __half2 c = __hmul2(*reinterpret_cast<__half2*>(&v.z), d2);
    __half2 d = __hmul2(*reinterpret_cast<__half2*>(&v.w), d2);
    uint4 o = make_uint4(*reinterpret_cast<uint32_t*>(&a), *reinterpret_cast<uint32_t*>(&b),
                         *reinterpret_cast<uint32_t*>(&c), *reinterpret_cast<uint32_t*>(&d));
    *p = o;
}

// ---------------- fused pull1 + relu + dot(W2): half-warp per dest ----------------
// h1h holds dinv[node]*h1 -> no per-edge dinv gather needed.
__global__ void __launch_bounds__(256) k_pull1(const float* __restrict__ b1,
                                               const float* __restrict__ W2) {
    int hw = (blockIdx.x * blockDim.x + threadIdx.x) >> 4;
    int l = threadIdx.x & 15;
    if (hw >= NN) return;
    int c = hw;
    int cnt = min(g_fill[c], CAP);
    float dc = g_dinv[c];
    unsigned hm = 0xFFFFu << (threadIdx.x & 16);

    float4 acc = make_float4(0.f, 0.f, 0.f, 0.f);
    const int2* eb = &g_edge[(size_t)c * CAP];

    int i = 0;
    for (; i + 4 <= cnt; i += 4) {
        int2 e0 = eb[i], e1 = eb[i + 1], e2 = eb[i + 2], e3 = eb[i + 3];
        float w0 = __int_as_float(e0.y);
        float w1 = __int_as_float(e1.y);
        float w2 = __int_as_float(e2.y);
        float w3 = __int_as_float(e3.y);
        uint2 p0 = *reinterpret_cast<const uint2*>(&g_h1h[(size_t)e0.x * FF + l * 4]);
        uint2 p1 = *reinterpret_cast<const uint2*>(&g_h1h[(size_t)e1.x * FF + l * 4]);
        uint2 p2 = *reinterpret_cast<const uint2*>(&g_h1h[(size_t)e2.x * FF + l * 4]);
        uint2 p3 = *reinterpret_cast<const uint2*>(&g_h1h[(size_t)e3.x * FF + l * 4]);
        float2 a0 = __half22float2(*reinterpret_cast<__half2*>(&p0.x));
        float2 c0 = __half22float2(*reinterpret_cast<__half2*>(&p0.y));
        float2 a1 = __half22float2(*reinterpret_cast<__half2*>(&p1.x));
        float2 c1 = __half22float2(*reinterpret_cast<__half2*>(&p1.y));
        float2 a2 = __half22float2(*reinterpret_cast<__half2*>(&p2.x));
        float2 c2 = __half22float2(*reinterpret_cast<__half2*>(&p2.y));
        float2 a3 = __half22float2(*reinterpret_cast<__half2*>(&p3.x));
        float2 c3 = __half22float2(*reinterpret_cast<__half2*>(&p3.y));
        acc.x = fmaf(w0, a0.x, acc.x); acc.y = fmaf(w0, a0.y, acc.y);
        acc.z = fmaf(w0, c0.x, acc.z); acc.w = fmaf(w0, c0.y, acc.w);
        acc.x = fmaf(w1, a1.x, acc.x); acc.y = fmaf(w1, a1.y, acc.y);
        acc.z = fmaf(w1, c1.x, acc.z); acc.w = fmaf(w1, c1.y, acc.w);
        acc.x = fmaf(w2, a2.x, acc.x); acc.y = fmaf(w2, a2.y, acc.y);
        acc.z = fmaf(w2, c2.x, acc.z); acc.w = fmaf(w2, c2.y, acc.w);
        acc.x = fmaf(w3, a3.x, acc.x); acc.y = fmaf(w3, a3.y, acc.y);
        acc.z = fmaf(w3, c3.x, acc.z); acc.w = fmaf(w3, c3.y, acc.w);
    }
    for (; i < cnt; i++) {
        int2 ev = eb[i];
        float wn = __int_as_float(ev.y);
        uint2 p = *reinterpret_cast<const uint2*>(&g_h1h[(size_t)ev.x * FF + l * 4]);
        float2 f0 = __half22float2(*reinterpret_cast<__half2*>(&p.x));
        float2 f1 = __half22float2(*reinterpret_cast<__half2*>(&p.y));
        acc.x = fmaf(wn, f0.x, acc.x); acc.y = fmaf(wn, f0.y, acc.y);
        acc.z = fmaf(wn, f1.x, acc.z); acc.w = fmaf(wn, f1.y, acc.w);
    }
    // self loop: h1h[c] == dc*h1[c] is exactly the inner self-loop term; add plain, outer *dc
    {
        uint2 p = *reinterpret_cast<const uint2*>(&g_h1h[(size_t)c * FF + l * 4]);
        float2 f0 = __half22float2(*reinterpret_cast<__half2*>(&p.x));
        float2 f1 = __half22float2(*reinterpret_cast<__half2*>(&p.y));
        acc.x = (acc.x + f0.x) * dc;
        acc.y = (acc.y + f0.y) * dc;
        acc.z = (acc.z + f1.x) * dc;
        acc.w = (acc.w + f1.y) * dc;
    }

    // fused layer-2 linear, pre-scaled by dinv[c]
    float4 bv = *reinterpret_cast<const float4*>(&b1[l * 4]);
    float4 wv = *reinterpret_cast<const float4*>(&W2[l * 4]);
    float s2 = fmaxf(acc.x + bv.x, 0.f) * wv.x
             + fmaxf(acc.y + bv.y, 0.f) * wv.y
             + fmaxf(acc.z + bv.z, 0.f) * wv.z
             + fmaxf(acc.w + bv.w, 0.f) * wv.w;
#pragma unroll
    for (int o = 8; o; o >>= 1) s2 += __shfl_xor_sync(hm, s2, o, 32);
    if (l == 0) g_h2[c] = s2 * dc;
}

// ---------------- layer 2 pull: 8 lanes per destination ----------------
__global__ void __launch_bounds__(256) k_pull2(const float* __restrict__ b2,
                                               float* __restrict__ out) {
    int oc = (blockIdx.x * blockDim.x + threadIdx.x) >> 3;
    int l = threadIdx.x & 7;
    if (oc >= NN) return;
    int c = oc;
    int cnt = min(g_fill[c], CAP);
    float dc = g_dinv[c];
    unsigned om = 0xFFu << (threadIdx.x & 24);
    size_t slot = (size_t)c * CAP;

    float s = 0.f;
    for (int i = l; i < cnt; i += 8) {
        int2 ev = g_edge[slot + i];
        s = fmaf(__int_as_float(ev.y), g_h2[ev.x], s);   // g_h2 has dinv[src] folded
    }
#pragma unroll
    for (int o = 4; o; o >>= 1) s += __shfl_down_sync(om, s, o, 8);
    if (l == 0) out[c] = (s + g_h2[c]) * dc + b2[0];
}

extern "C" void kernel_launch(void* const* d_in, const int* in_sizes, int n_in,
                              void* d_out, int out_size) {
    const float* x  = (const float*)d_in[0];
    const int*   ei = (const int*)d_in[1];
    const float* ew = (const float*)d_in[2];
    const float* W1 = (const float*)d_in[3];
    const float* b1 = (const float*)d_in[4];
    const float* W2 = (const float*)d_in[5];
    const float* b2 = (const float*)d_in[6];
    float* out = (float*)d_out;

    const int* row = ei;
    const int* col = ei + EE;

    k_init<<<(NN + 255) / 256, 256>>>();
    k_gemm_fill<<<FAT_GRID, 256>>>(x, W1, row, col, ew);  // gemm + fill co-scheduled
    k_dinv_scale<<<(NN * 8 + 255) / 256, 256>>>();        // dinv + fold into h1h (uint4!)
    {
        long long threads = (long long)NN * 16;
        k_pull1<<<(int)((threads + 255) / 256), 256>>>(b1, W2);
    }
    {
        long long threads = (long long)NN * 8;
        k_pull2<<<(int)((threads + 255) / 256), 256>>>(b2, out);
    }
}

// round 13
// speedup vs baseline: 1.0246x; 1.0246x over previous
#include <cuda_runtime.h>
#include <cuda_fp16.h>
#include <cstdint>

#define NN 100000
#define EE 1280000
#define FF 64
#define CAP 64   // per-node in-edge capacity; P(overflow) ~ 1e-20 for multinomial(12.8)

#define GEMM_BLOCKS ((NN + 63) / 64)       // 1563
#define FILL_BLOCKS ((EE / 4 + 255) / 256) // 1250
#define FAT_GRID (2 * GEMM_BLOCKS)         // even -> gemm, odd -> fill (tail idles)

__device__ float  g_deg[NN];
__device__ float  g_dinv[NN];
__device__ int    g_fill[NN];
__device__ int2   g_edge[(size_t)NN * CAP];   // {src, bitcast(w)}
__device__ __half g_h1h[(size_t)NN * FF];     // fp16 x@W1 (raw)
__device__ float  g_h2[NN];                   // relu-dot * dinv[node]

// ---------------- init ----------------
__global__ void k_init() {
    int i = blockIdx.x * blockDim.x + threadIdx.x;
    if (i < NN) { g_fill[i] = 0; g_deg[i] = 0.0f; }
}

// ---------------- fused GEMM + bucket-fill fat kernel ----------------
__global__ void __launch_bounds__(256) k_gemm_fill(const float* __restrict__ x,
                                                   const float* __restrict__ W1,
                                                   const int* __restrict__ row,
                                                   const int* __restrict__ col,
                                                   const float* __restrict__ w) {
    __shared__ float sW[FF * FF];
    __shared__ float sx[64][68];
    int t = threadIdx.x;

    if (blockIdx.x & 1) {
        // ---------- fill role ----------
        int fb = blockIdx.x >> 1;
        if (fb >= FILL_BLOCKS) return;
        int e4 = fb * 256 + t;               // 0 .. EE/4-1
        if (e4 >= EE / 4) return;
        int4 r4 = reinterpret_cast<const int4*>(row)[e4];
        int4 c4 = reinterpret_cast<const int4*>(col)[e4];
        float4 w4 = reinterpret_cast<const float4*>(w)[e4];
        int r[4] = {r4.x, r4.y, r4.z, r4.w};
        int c[4] = {c4.x, c4.y, c4.z, c4.w};
        float ww[4] = {w4.x, w4.y, w4.z, w4.w};
        int pos[4];
#pragma unroll
        for (int i = 0; i < 4; i++) pos[i] = atomicAdd(&g_fill[c[i]], 1);
#pragma unroll
        for (int i = 0; i < 4; i++) {
            asm volatile("red.global.add.f32 [%0], %1;"
                         :: "l"(&g_deg[c[i]]), "f"(ww[i]) : "memory");
            if (pos[i] < CAP)
                g_edge[(size_t)c[i] * CAP + pos[i]] = make_int2(r[i], __float_as_int(ww[i]));
        }
        return;
    }

    // ---------- gemm role ----------
    int gb = blockIdx.x >> 1;
    int nb = gb * 64;

    {
        const float4* Wv = reinterpret_cast<const float4*>(W1);
        float4* sWv = reinterpret_cast<float4*>(sW);
#pragma unroll
        for (int i = 0; i < 4; i++) sWv[t + i * 256] = Wv[t + i * 256];
    }
#pragma unroll
    for (int i = 0; i < 4; i++) {
        int idx = t + i * 256;
        int nl = idx >> 4, kv = idx & 15;
        int node = nb + nl;
        float4 v = make_float4(0.f, 0.f, 0.f, 0.f);
        if (node < NN) v = reinterpret_cast<const float4*>(x)[(size_t)node * 16 + kv];
        *reinterpret_cast<float4*>(&sx[nl][kv * 4]) = v;
    }
    __syncthreads();

    int tx = t & 15;
    int ty = t >> 4;

    float4 acc[4];
#pragma unroll
    for (int i = 0; i < 4; i++) acc[i] = make_float4(0.f, 0.f, 0.f, 0.f);

#pragma unroll
    for (int kb = 0; kb < 16; kb++) {
        float4 xr[4];
#pragma unroll
        for (int i = 0; i < 4; i++)
            xr[i] = *reinterpret_cast<const float4*>(&sx[4 * ty + i][4 * kb]);
#pragma unroll
        for (int kk = 0; kk < 4; kk++) {
            float4 wv = *reinterpret_cast<const float4*>(&sW[(4 * kb + kk) * FF + 4 * tx]);
            float xv0 = (kk == 0) ? xr[0].x : (kk == 1) ? xr[0].y : (kk == 2) ? xr[0].z : xr[0].w;
            float xv1 = (kk == 0) ? xr[1].x : (kk == 1) ? xr[1].y : (kk == 2) ? xr[1].z : xr[1].w;
            float xv2 = (kk == 0) ? xr[2].x : (kk == 1) ? xr[2].y : (kk == 2) ? xr[2].z : xr[2].w;
            float xv3 = (kk == 0) ? xr[3].x : (kk == 1) ? xr[3].y : (kk == 2) ? xr[3].z : xr[3].w;
            acc[0].x = fmaf(xv0, wv.x, acc[0].x); acc[0].y = fmaf(xv0, wv.y, acc[0].y);
            acc[0].z = fmaf(xv0, wv.z, acc[0].z); acc[0].w = fmaf(xv0, wv.w, acc[0].w);
            acc[1].x = fmaf(xv1, wv.x, acc[1].x); acc[1].y = fmaf(xv1, wv.y, acc[1].y);
            acc[1].z = fmaf(xv1, wv.z, acc[1].z); acc[1].w = fmaf(xv1, wv.w, acc[1].w);
            acc[2].x = fmaf(xv2, wv.x, acc[2].x); acc[2].y = fmaf(xv2, wv.y, acc[2].y);
            acc[2].z = fmaf(xv2, wv.z, acc[2].z); acc[2].w = fmaf(xv2, wv.w, acc[2].w);
            acc[3].x = fmaf(xv3, wv.x, acc[3].x); acc[3].y = fmaf(xv3, wv.y, acc[3].y);
            acc[3].z = fmaf(xv3, wv.z, acc[3].z); acc[3].w = fmaf(xv3, wv.w, acc[3].w);
        }
    }

#pragma unroll
    for (int i = 0; i < 4; i++) {
        int node = nb + 4 * ty + i;
        if (node >= NN) continue;
        __half2 h01 = __floats2half2_rn(acc[i].x, acc[i].y);
        __half2 h23 = __floats2half2_rn(acc[i].z, acc[i].w);
        uint2 p = make_uint2(*reinterpret_cast<uint32_t*>(&h01),
                             *reinterpret_cast<uint32_t*>(&h23));
        *reinterpret_cast<uint2*>(&g_h1h[(size_t)node * FF + 4 * tx]) = p;
    }
}

// ---------------- dinv: trivial ----------------
__global__ void k_dinv() {
    int i = blockIdx.x * blockDim.x + threadIdx.x;
    if (i < NN) g_dinv[i] = rsqrtf(g_deg[i] + 1.0f);   // + self-loop weight
}

// ---------------- fused pull1 + relu + dot(W2): half-warp per dest, unroll 8 ----------------
__global__ void __launch_bounds__(256) k_pull1(const float* __restrict__ b1,
                                               const float* __restrict__ W2) {
    int hw = (blockIdx.x * blockDim.x + threadIdx.x) >> 4;
    int l = threadIdx.x & 15;
    if (hw >= NN) return;
    int c = hw;
    int cnt = min(g_fill[c], CAP);
    float dc = g_dinv[c];
    unsigned hm = 0xFFFFu << (threadIdx.x & 16);

    float4 acc = make_float4(0.f, 0.f, 0.f, 0.f);
    const int2* eb = &g_edge[(size_t)c * CAP];

    int i = 0;
    for (; i + 8 <= cnt; i += 8) {
        int2 e[8];
#pragma unroll
        for (int j = 0; j < 8; j++) e[j] = eb[i + j];
        float wn[8];
#pragma unroll
        for (int j = 0; j < 8; j++) wn[j] = __int_as_float(e[j].y) * g_dinv[e[j].x];
        uint2 p[8];
#pragma unroll
        for (int j = 0; j < 8; j++)
            p[j] = *reinterpret_cast<const uint2*>(&g_h1h[(size_t)e[j].x * FF + l * 4]);
#pragma unroll
        for (int j = 0; j < 8; j++) {
            float2 f0 = __half22float2(*reinterpret_cast<__half2*>(&p[j].x));
            float2 f1 = __half22float2(*reinterpret_cast<__half2*>(&p[j].y));
            acc.x = fmaf(wn[j], f0.x, acc.x); acc.y = fmaf(wn[j], f0.y, acc.y);
            acc.z = fmaf(wn[j], f1.x, acc.z); acc.w = fmaf(wn[j], f1.y, acc.w);
        }
    }
    if (i + 4 <= cnt) {
        int2 e[4];
#pragma unroll
        for (int j = 0; j < 4; j++) e[j] = eb[i + j];
        float wn[4];
#pragma unroll
        for (int j = 0; j < 4; j++) wn[j] = __int_as_float(e[j].y) * g_dinv[e[j].x];
        uint2 p[4];
#pragma unroll
        for (int j = 0; j < 4; j++)
            p[j] = *reinterpret_cast<const uint2*>(&g_h1h[(size_t)e[j].x * FF + l * 4]);
#pragma unroll
        for (int j = 0; j < 4; j++) {
            float2 f0 = __half22float2(*reinterpret_cast<__half2*>(&p[j].x));
            float2 f1 = __half22float2(*reinterpret_cast<__half2*>(&p[j].y));
            acc.x = fmaf(wn[j], f0.x, acc.x); acc.y = fmaf(wn[j], f0.y, acc.y);
            acc.z = fmaf(wn[j], f1.x, acc.z); acc.w = fmaf(wn[j], f1.y, acc.w);
        }
        i += 4;
    }
    for (; i < cnt; i++) {
        int2 ev = eb[i];
        float wn = __int_as_float(ev.y) * g_dinv[ev.x];
        uint2 p = *reinterpret_cast<const uint2*>(&g_h1h[(size_t)ev.x * FF + l * 4]);
        float2 f0 = __half22float2(*reinterpret_cast<__half2*>(&p.x));
        float2 f1 = __half22float2(*reinterpret_cast<__half2*>(&p.y));
        acc.x = fmaf(wn, f0.x, acc.x); acc.y = fmaf(wn, f0.y, acc.y);
        acc.z = fmaf(wn, f1.x, acc.z); acc.w = fmaf(wn, f1.y, acc.w);
    }
    // self loop: inner term dc*h1[c], then outer *dc
    {
        uint2 p = *reinterpret_cast<const uint2*>(&g_h1h[(size_t)c * FF + l * 4]);
        float2 f0 = __half22float2(*reinterpret_cast<__half2*>(&p.x));
        float2 f1 = __half22float2(*reinterpret_cast<__half2*>(&p.y));
        acc.x = fmaf(dc, f0.x, acc.x) * dc;
        acc.y = fmaf(dc, f0.y, acc.y) * dc;
        acc.z = fmaf(dc, f1.x, acc.z) * dc;
        acc.w = fmaf(dc, f1.y, acc.w) * dc;
    }

    // fused layer-2 linear, pre-scaled by dinv[c]
    float4 bv = *reinterpret_cast<const float4*>(&b1[l * 4]);
    float4 wv = *reinterpret_cast<const float4*>(&W2[l * 4]);
    float s2 = fmaxf(acc.x + bv.x, 0.f) * wv.x
             + fmaxf(acc.y + bv.y, 0.f) * wv.y
             + fmaxf(acc.z + bv.z, 0.f) * wv.z
             + fmaxf(acc.w + bv.w, 0.f) * wv.w;
#pragma unroll
    for (int o = 8; o; o >>= 1) s2 += __shfl_xor_sync(hm, s2, o, 32);
    if (l == 0) g_h2[c] = s2 * dc;
}

// ---------------- layer 2 pull: 8 lanes per destination ----------------
__global__ void __launch_bounds__(256) k_pull2(const float* __restrict__ b2,
                                               float* __restrict__ out) {
    int oc = (blockIdx.x * blockDim.x + threadIdx.x) >> 3;
    int l = threadIdx.x & 7;
    if (oc >= NN) return;
    int c = oc;
    int cnt = min(g_fill[c], CAP);
    float dc = g_dinv[c];
    unsigned om = 0xFFu << (threadIdx.x & 24);
    size_t slot = (size_t)c * CAP;

    float s = 0.f;
    for (int i = l; i < cnt; i += 8) {
        int2 ev = g_edge[slot + i];
        s = fmaf(__int_as_float(ev.y), g_h2[ev.x], s);   // g_h2 has dinv[src] folded
    }
#pragma unroll
    for (int o = 4; o; o >>= 1) s += __shfl_down_sync(om, s, o, 8);
    if (l == 0) out[c] = (s + g_h2[c]) * dc + b2[0];
}

extern "C" void kernel_launch(void* const* d_in, const int* in_sizes, int n_in,
                              void* d_out, int out_size) {
    const float* x  = (const float*)d_in[0];
    const int*   ei = (const int*)d_in[1];
    const float* ew = (const float*)d_in[2];
    const float* W1 = (const float*)d_in[3];
    const float* b1 = (const float*)d_in[4];
    const float* W2 = (const float*)d_in[5];
    const float* b2 = (const float*)d_in[6];
    float* out = (float*)d_out;

    const int* row = ei;
    const int* col = ei + EE;

    k_init<<<(NN + 255) / 256, 256>>>();
    k_gemm_fill<<<FAT_GRID, 256>>>(x, W1, row, col, ew);  // gemm + fill co-scheduled
    k_dinv<<<(NN + 255) / 256, 256>>>();
    {
        long long threads = (long long)NN * 16;
        k_pull1<<<(int)((threads + 255) / 256), 256>>>(b1, W2);
    }
    {
        long long threads = (long long)NN * 8;
        k_pull2<<<(int)((threads + 255) / 256), 256>>>(b2, out);
    }
}